// round 16
// baseline (speedup 1.0000x reference)
#include <cuda_runtime.h>
#include <float.h>
#include <math.h>

#define BB 8
#define MAXN 1024
#define MAXC 512
#define EPSV 1e-10f
#define MUSL 8

// level offsets into packed point buffers (floats):
// l0: 8*1000*64 = 512000, l1: 8*1000*128 = 1024000,
// l2: 8*1000*256 = 2048000, l3: 8*1024*512 = 4194304  -> total 7778304
__device__ __forceinline__ size_t lvl_off(int l) {
    return (l == 0) ? 0ul : (l == 1) ? 512000ul : (l == 2) ? 1536000ul : 3584000ul;
}

// ------------------------- scratch (static device globals) -----------------
__device__ __align__(128) float g_X[7778304];
__device__ __align__(128) float g_Y[7778304];
__device__ float g_xn[4 * BB * MAXN];
__device__ float g_yn[4 * BB * MAXN];
__device__ float g_rowmin[4 * BB * MAXN];
__device__ float g_colmin[4 * BB * MAXN];
__device__ float g_muxp[MUSL][4 * BB * MAXC];
__device__ float g_muyp[MUSL][4 * BB * MAXC];
__device__ float g_mux[4 * BB * MAXC];
__device__ float g_muy[4 * BB * MAXC];
__device__ float g_mud[4 * BB];
__device__ float g_covsum[4 * BB];
__device__ float g_m1[4 * BB];
__device__ float g_m2[4 * BB];

// ------------------------------ helpers ------------------------------------
__device__ __forceinline__ void atomicMinF(float* addr, float val) {
    if (val >= 0.f) atomicMin((int*)addr, __float_as_int(val));
    else            atomicMax((unsigned int*)addr, __float_as_uint(val));
}

__device__ __forceinline__ float blockReduceSum(float v, float* sbuf) {
    int t = threadIdx.x + threadIdx.y * blockDim.x;
    int nt = blockDim.x * blockDim.y;
    __syncthreads();
    sbuf[t] = v;
    __syncthreads();
    for (int s = nt >> 1; s > 0; s >>= 1) {
        if (t < s) sbuf[t] += sbuf[t + s];
        __syncthreads();
    }
    return sbuf[0];
}

// ------------------------------ init ----------------------------------------
__global__ void k_init() {
    int i = blockIdx.x * blockDim.x + threadIdx.x;
    if (i < 4 * BB * MAXN) {
        g_rowmin[i] = FLT_MAX;
        g_colmin[i] = FLT_MAX;
    }
    if (i < 4 * BB) g_covsum[i] = 0.f;
}

// --------------------- gather + norms (levels 0-2, one launch) --------------
__global__ void k_gather_all(const float* __restrict__ tf0, const float* __restrict__ gf0, const int* __restrict__ ix0,
                             const float* __restrict__ tf1, const float* __restrict__ gf1, const int* __restrict__ ix1,
                             const float* __restrict__ tf2, const float* __restrict__ gf2, const int* __restrict__ ix2) {
    __shared__ float sbuf[128];
    int i = blockIdx.x;          // 0..999
    int z = blockIdx.y;          // lvl*8 + b
    int lvl = z >> 3, b = z & 7;
    const float* tf; const float* gf; const int* idx; int c, hw;
    if (lvl == 0)      { tf = tf0; gf = gf0; idx = ix0; c = 64;  hw = 65536; }
    else if (lvl == 1) { tf = tf1; gf = gf1; idx = ix1; c = 128; hw = 16384; }
    else               { tf = tf2; gf = gf2; idx = ix2; c = 256; hw = 4096; }
    const int N = 1000;
    int p = idx[b * N + i];
    const float* ts = tf + (size_t)b * c * hw + p;
    const float* gs = gf + (size_t)b * c * hw + p;
    size_t base = lvl_off(lvl) + ((size_t)b * N + i) * c;
    float sx = 0.f, sy = 0.f;
    for (int ch = threadIdx.x; ch < c; ch += 128) {
        float v = ts[(size_t)ch * hw];
        float w = gs[(size_t)ch * hw];
        g_X[base + ch] = v;
        g_Y[base + ch] = w;
        sx += v * v;
        sy += w * w;
    }
    float tx_ = blockReduceSum(sx, sbuf);
    float ty_ = blockReduceSum(sy, sbuf);
    if (threadIdx.x == 0) {
        g_xn[z * MAXN + i] = sqrtf(tx_);
        g_yn[z * MAXN + i] = sqrtf(ty_);
    }
}

// ------------------------------ level-3 transpose ---------------------------
__global__ void k_transpose3(const float* __restrict__ tf, const float* __restrict__ gf) {
    __shared__ float st[32][33];
    __shared__ float sg[32][33];
    int b  = blockIdx.z;
    int i0 = blockIdx.x << 5;
    int c0 = blockIdx.y << 5;
    int tx = threadIdx.x;
    int ty = threadIdx.y;
    const float* tb = tf + ((size_t)(b * 512 + c0)) * 1024 + i0;
    const float* gb = gf + ((size_t)(b * 512 + c0)) * 1024 + i0;
    for (int r = ty; r < 32; r += 8) {
        st[r][tx] = tb[(size_t)r * 1024 + tx];
        sg[r][tx] = gb[(size_t)r * 1024 + tx];
    }
    __syncthreads();
    size_t base = 3584000ul + (size_t)b * 524288ul;
    for (int r = ty; r < 32; r += 8) {
        g_X[base + (size_t)(i0 + r) * 512 + c0 + tx] = st[tx][r];
        g_Y[base + (size_t)(i0 + r) * 512 + c0 + tx] = sg[tx][r];
    }
}

// ------------------------ norms for level 3 (from original layout) ----------
__global__ void k_norms3(const float* __restrict__ tf, const float* __restrict__ gf) {
    __shared__ float sx[8][33], sy[8][33];
    int b  = blockIdx.y;
    int i0 = blockIdx.x << 5;
    int tx = threadIdx.x, ty = threadIdx.y;
    const float* tb = tf + (size_t)b * 512 * 1024 + i0 + tx;
    const float* gb = gf + (size_t)b * 512 * 1024 + i0 + tx;
    float ax = 0.f, ay = 0.f;
    for (int ch = ty; ch < 512; ch += 8) {
        float v = tb[(size_t)ch * 1024]; ax += v * v;
        float w = gb[(size_t)ch * 1024]; ay += w * w;
    }
    sx[ty][tx] = ax;
    sy[ty][tx] = ay;
    __syncthreads();
    if (ty == 0) {
        float a = 0.f, c2 = 0.f;
#pragma unroll
        for (int k = 0; k < 8; k++) { a += sx[k][tx]; c2 += sy[k][tx]; }
        int z = 3 * BB + b;
        g_xn[z * MAXN + i0 + tx] = sqrtf(a);
        g_yn[z * MAXN + i0 + tx] = sqrtf(c2);
    }
}

// ------------------------------ mu partial sums (all levels) ----------------
__global__ void k_musum_all() {
    __shared__ float shx[8][64], shy[8][64];
    int z   = blockIdx.z;        // lvl*8 + b
    int lvl = z >> 3, b = z & 7;
    int c = 64 << lvl;
    int N = (lvl == 3) ? 1024 : 1000;
    if ((blockIdx.x << 6) >= c) return;
    int sl = blockIdx.y;
    int ch = (blockIdx.x << 6) + threadIdx.x;
    int len = (N + MUSL - 1) / MUSL;
    int r0 = sl * len;
    int r1 = min(N, r0 + len);
    const float* x = g_X + lvl_off(lvl) + (size_t)b * N * c + ch;
    const float* y = g_Y + lvl_off(lvl) + (size_t)b * N * c + ch;
    float sx = 0.f, sy = 0.f;
    for (int i = r0 + threadIdx.y; i < r1; i += 8) {
        sx += x[(size_t)i * c];
        sy += y[(size_t)i * c];
    }
    shx[threadIdx.y][threadIdx.x] = sx;
    shy[threadIdx.y][threadIdx.x] = sy;
    __syncthreads();
    if (threadIdx.y == 0) {
        float ax = 0.f, ay = 0.f;
#pragma unroll
        for (int k = 0; k < 8; k++) { ax += shx[k][threadIdx.x]; ay += shy[k][threadIdx.x]; }
        g_muxp[sl][z * MAXC + ch] = ax;
        g_muyp[sl][z * MAXC + ch] = ay;
    }
}

// ------------------------------ mu finalize + mu_d (all levels) -------------
__global__ void k_mufin_all() {
    __shared__ float sbuf[512];
    int z   = blockIdx.x;        // lvl*8 + b
    int lvl = z >> 3;
    int c = 64 << lvl;
    int N = (lvl == 3) ? 1024 : 1000;
    int p = threadIdx.x;
    float v = 0.f;
    if (p < c) {
        float sx = 0.f, sy = 0.f;
#pragma unroll
        for (int s = 0; s < MUSL; s++) {
            sx += g_muxp[s][z * MAXC + p];
            sy += g_muyp[s][z * MAXC + p];
        }
        float mx = sx / (float)N, my = sy / (float)N;
        g_mux[z * MAXC + p] = mx;
        g_muy[z * MAXC + p] = my;
        v = fabsf(mx - my);
    }
    float tot = blockReduceSum(v, sbuf);
    if (p == 0) g_mud[z] = tot / (float)c;
}

// ======================= fused main: style GEMM + cov GEMM ==================
// Block schedule (expensive first): cov-l3(288), style-l3(512), cov-l2(80),
// style-l2(512), cov-l1(24), style-l1(512), cov-l0(8), style-l0(512) = 2448.
__global__ void __launch_bounds__(256) k_main() {
    __shared__ float SH[4608];
    int bid = blockIdx.x;
    int t = threadIdx.x;
    int tx = t & 15, ty = t >> 4;

    bool isStyle;
    int lvl, b, rem;   // style: rem = tile index 0..63 ; cov: rem = pair id
    if (bid < 288)        { isStyle = false; lvl = 3; b = bid & 7;            rem = bid >> 3; }
    else if (bid < 800)   { isStyle = true;  lvl = 3; int s = bid - 288;  b = s >> 6; rem = s & 63; }
    else if (bid < 880)   { isStyle = false; lvl = 2; int s = bid - 800;  b = s & 7;  rem = s >> 3; }
    else if (bid < 1392)  { isStyle = true;  lvl = 2; int s = bid - 880;  b = s >> 6; rem = s & 63; }
    else if (bid < 1416)  { isStyle = false; lvl = 1; int s = bid - 1392; b = s & 7;  rem = s >> 3; }
    else if (bid < 1928)  { isStyle = true;  lvl = 1; int s = bid - 1416; b = s >> 6; rem = s & 63; }
    else if (bid < 1936)  { isStyle = false; lvl = 0; int s = bid - 1928; b = s & 7;  rem = 0; }
    else                  { isStyle = true;  lvl = 0; int s = bid - 1936; b = s >> 6; rem = s & 63; }

    int c = 64 << lvl;
    int N = (lvl == 3) ? 1024 : 1000;
    int zi = lvl * BB + b;
    const float* X = g_X + lvl_off(lvl) + (size_t)b * N * c;
    const float* Y = g_Y + lvl_off(lvl) + (size_t)b * N * c;
    float4 z4 = make_float4(0.f, 0.f, 0.f, 0.f);

    if (isStyle) {
        // ---------- style: 128x128 tile, BK=8, double-buffered, 8x8 micro ----
        float* As   = SH;               // [2][8][132] = 2112
        float* Bs   = SH + 2112;        // 2112
        float* sRow = SH + 4224;        // 128
        float* sCol = SH + 4352;        // 128
        int i0 = (rem >> 3) << 7;
        int j0 = (rem & 7) << 7;
        int lr = t >> 1;
        int lk = (t & 1) << 2;
        int gi = i0 + lr, gj = j0 + lr;
        const float* xp = X + (size_t)gi * c + lk;
        const float* yp = Y + (size_t)gj * c + lk;

        float acc[8][8];
#pragma unroll
        for (int ii = 0; ii < 8; ii++)
#pragma unroll
            for (int jj = 0; jj < 8; jj++) acc[ii][jj] = 0.f;

        if (t < 128) { sRow[t] = FLT_MAX; sCol[t] = FLT_MAX; }

        // preload tile 0 into buffer 0
        {
            float4 cA = (gi < N) ? *reinterpret_cast<const float4*>(xp) : z4;
            float4 cB = (gj < N) ? *reinterpret_cast<const float4*>(yp) : z4;
            As[(lk + 0) * 132 + lr] = cA.x; As[(lk + 1) * 132 + lr] = cA.y;
            As[(lk + 2) * 132 + lr] = cA.z; As[(lk + 3) * 132 + lr] = cA.w;
            Bs[(lk + 0) * 132 + lr] = cB.x; Bs[(lk + 1) * 132 + lr] = cB.y;
            Bs[(lk + 2) * 132 + lr] = cB.z; Bs[(lk + 3) * 132 + lr] = cB.w;
        }
        __syncthreads();

        for (int k0 = 0; k0 < c; k0 += 8) {
            int buf = (k0 >> 3) & 1;
            int kn = k0 + 8;
            float4 nA = z4, nB = z4;
            if (kn < c) {
                nA = (gi < N) ? *reinterpret_cast<const float4*>(xp + kn) : z4;
                nB = (gj < N) ? *reinterpret_cast<const float4*>(yp + kn) : z4;
            }
            const float* A = As + buf * 1056;
            const float* B = Bs + buf * 1056;
#pragma unroll
            for (int kk = 0; kk < 8; kk++) {
                float4 a0 = *reinterpret_cast<const float4*>(&A[kk * 132 + (tx << 3)]);
                float4 a1 = *reinterpret_cast<const float4*>(&A[kk * 132 + (tx << 3) + 4]);
                float4 b0 = *reinterpret_cast<const float4*>(&B[kk * 132 + (ty << 3)]);
                float4 b1 = *reinterpret_cast<const float4*>(&B[kk * 132 + (ty << 3) + 4]);
                float aa[8] = {a0.x, a0.y, a0.z, a0.w, a1.x, a1.y, a1.z, a1.w};
                float bb[8] = {b0.x, b0.y, b0.z, b0.w, b1.x, b1.y, b1.z, b1.w};
#pragma unroll
                for (int ii = 0; ii < 8; ii++)
#pragma unroll
                    for (int jj = 0; jj < 8; jj++)
                        acc[ii][jj] += aa[ii] * bb[jj];
            }
            if (kn < c) {
                float* An = As + (buf ^ 1) * 1056;
                float* Bn = Bs + (buf ^ 1) * 1056;
                An[(lk + 0) * 132 + lr] = nA.x; An[(lk + 1) * 132 + lr] = nA.y;
                An[(lk + 2) * 132 + lr] = nA.z; An[(lk + 3) * 132 + lr] = nA.w;
                Bn[(lk + 0) * 132 + lr] = nB.x; Bn[(lk + 1) * 132 + lr] = nB.y;
                Bn[(lk + 2) * 132 + lr] = nB.z; Bn[(lk + 3) * 132 + lr] = nB.w;
            }
            __syncthreads();
        }

        float rn[8], cn[8];
#pragma unroll
        for (int ii = 0; ii < 8; ii++) {
            int i = i0 + (tx << 3) + ii;
            rn[ii] = (i < N) ? g_xn[zi * MAXN + i] : 0.f;
        }
#pragma unroll
        for (int jj = 0; jj < 8; jj++) {
            int j = j0 + (ty << 3) + jj;
            cn[jj] = (j < N) ? g_yn[zi * MAXN + j] : 0.f;
        }

        float rmin[8], cmin[8];
#pragma unroll
        for (int q = 0; q < 8; q++) { rmin[q] = FLT_MAX; cmin[q] = FLT_MAX; }
#pragma unroll
        for (int ii = 0; ii < 8; ii++) {
            int i = i0 + (tx << 3) + ii;
#pragma unroll
            for (int jj = 0; jj < 8; jj++) {
                int j = j0 + (ty << 3) + jj;
                float d = FLT_MAX;
                if (i < N && j < N)
                    d = 1.f - acc[ii][jj] / ((rn[ii] + EPSV) * (cn[jj] + EPSV));
                rmin[ii] = fminf(rmin[ii], d);
                cmin[jj] = fminf(cmin[jj], d);
            }
        }
#pragma unroll
        for (int ii = 0; ii < 8; ii++) atomicMinF(&sRow[(tx << 3) + ii], rmin[ii]);
#pragma unroll
        for (int jj = 0; jj < 8; jj++) atomicMinF(&sCol[(ty << 3) + jj], cmin[jj]);
        __syncthreads();

        if (t < 128) {
            if (i0 + t < N) atomicMinF(&g_rowmin[zi * MAXN + i0 + t], sRow[t]);
            if (j0 + t < N) atomicMinF(&g_colmin[zi * MAXN + j0 + t], sCol[t]);
        }
    } else {
        // ---------- cov: 64x64 tile of (p,q), tp<=tq, BK=16, scalar ----------
        float* Xp   = SH;            // 16*68 = 1088
        float* Xq   = SH + 1088;
        float* Yp   = SH + 2176;
        float* Yq   = SH + 3264;
        float* sbuf = SH + 4352;     // 256

        int T = c >> 6;
        int tp = 0, r2 = rem;
        while (r2 >= T - tp) { r2 -= (T - tp); tp++; }
        int tq = tp + r2;
        int p0 = tp << 6, q0 = tq << 6;

        int lrow = t >> 4;
        int lcol = (t & 15) << 2;

        float ax[4][4], ay[4][4];
#pragma unroll
        for (int xi = 0; xi < 4; xi++)
#pragma unroll
            for (int yj = 0; yj < 4; yj++) { ax[xi][yj] = 0.f; ay[xi][yj] = 0.f; }

        for (int k0 = 0; k0 < N; k0 += 16) {
            int i = k0 + lrow;
            float4 v0 = z4, v1 = z4, v2 = z4, v3 = z4;
            if (i < N) {
                const float* xr = X + (size_t)i * c;
                const float* yr = Y + (size_t)i * c;
                v0 = *reinterpret_cast<const float4*>(xr + p0 + lcol);
                v1 = *reinterpret_cast<const float4*>(xr + q0 + lcol);
                v2 = *reinterpret_cast<const float4*>(yr + p0 + lcol);
                v3 = *reinterpret_cast<const float4*>(yr + q0 + lcol);
            }
            *reinterpret_cast<float4*>(&Xp[lrow * 68 + lcol]) = v0;
            *reinterpret_cast<float4*>(&Xq[lrow * 68 + lcol]) = v1;
            *reinterpret_cast<float4*>(&Yp[lrow * 68 + lcol]) = v2;
            *reinterpret_cast<float4*>(&Yq[lrow * 68 + lcol]) = v3;
            __syncthreads();
#pragma unroll
            for (int kk = 0; kk < 16; kk++) {
                float4 apv = *reinterpret_cast<const float4*>(&Xp[kk * 68 + (tx << 2)]);
                float4 aqv = *reinterpret_cast<const float4*>(&Xq[kk * 68 + (ty << 2)]);
                float4 bpv = *reinterpret_cast<const float4*>(&Yp[kk * 68 + (tx << 2)]);
                float4 bqv = *reinterpret_cast<const float4*>(&Yq[kk * 68 + (ty << 2)]);
                float ap[4] = {apv.x, apv.y, apv.z, apv.w};
                float aq[4] = {aqv.x, aqv.y, aqv.z, aqv.w};
                float bp[4] = {bpv.x, bpv.y, bpv.z, bpv.w};
                float bq[4] = {bqv.x, bqv.y, bqv.z, bqv.w};
#pragma unroll
                for (int xi = 0; xi < 4; xi++)
#pragma unroll
                    for (int yj = 0; yj < 4; yj++) {
                        ax[xi][yj] += ap[xi] * aq[yj];
                        ay[xi][yj] += bp[xi] * bq[yj];
                    }
            }
            __syncthreads();
        }

        float fn = (float)N;
        float inv = 1.f / (fn - 1.f);
        float mxp[4], mxq[4], myp[4], myq[4];
#pragma unroll
        for (int xi = 0; xi < 4; xi++) {
            int p = p0 + (tx << 2) + xi;
            mxp[xi] = g_mux[zi * MAXC + p];
            myp[xi] = g_muy[zi * MAXC + p];
        }
#pragma unroll
        for (int yj = 0; yj < 4; yj++) {
            int q = q0 + (ty << 2) + yj;
            mxq[yj] = g_mux[zi * MAXC + q];
            myq[yj] = g_muy[zi * MAXC + q];
        }
        float s = 0.f;
#pragma unroll
        for (int xi = 0; xi < 4; xi++)
#pragma unroll
            for (int yj = 0; yj < 4; yj++) {
                float gx = ax[xi][yj] - fn * mxp[xi] * mxq[yj];
                float gy = ay[xi][yj] - fn * myp[xi] * myq[yj];
                s += fabsf((gx - gy) * inv);
            }
        if (tp != tq) s *= 2.f;
        float tot = blockReduceSum(s, sbuf);
        if (t == 0) atomicAdd(&g_covsum[zi], tot);
    }
}

// ------------------------------ style means (all levels) --------------------
__global__ void k_minmeans_all() {
    __shared__ float sbuf[256];
    int z = blockIdx.x;          // lvl*8 + b
    int lvl = z >> 3;
    int N = (lvl == 3) ? 1024 : 1000;
    const float* rm = g_rowmin + (size_t)z * MAXN;
    const float* cm = g_colmin + (size_t)z * MAXN;
    float s1 = 0.f, s2 = 0.f;
    for (int i = threadIdx.x; i < N; i += 256) { s1 += rm[i]; s2 += cm[i]; }
    float t1 = blockReduceSum(s1, sbuf);
    float t2 = blockReduceSum(s2, sbuf);
    if (threadIdx.x == 0) {
        g_m1[z] = t1 / (float)N;
        g_m2[z] = t2 / (float)N;
    }
}

// ------------------------------ final ---------------------------------------
__global__ void k_final(float* out) {
    int t = threadIdx.x;
    float v = 0.f;
    if (t < 32) {
        int lvl = t >> 3;
        float cc = (float)(64 << lvl);
        float style = fmaxf(g_m1[t], g_m2[t]);
        v = style + g_mud[t] + g_covsum[t] / (cc * cc);
    }
#pragma unroll
    for (int o = 16; o > 0; o >>= 1) v += __shfl_down_sync(0xffffffff, v, o);
    if (t == 0) out[0] = v / (float)BB;
}

// ------------------------------ launch --------------------------------------
extern "C" void kernel_launch(void* const* d_in, const int* in_sizes, int n_in,
                              void* d_out, int out_size) {
    (void)out_size;
    const float* tf[4] = {0, 0, 0, 0};
    const float* gf[4] = {0, 0, 0, 0};
    const int* idxp[3] = {0, 0, 0};
    int tc[4] = {0, 0, 0, 0}, ic = 0;
    const long long lsz[4] = {33554432LL, 16777216LL, 8388608LL, 4194304LL};
    for (int i = 0; i < n_in; i++) {
        long long s = in_sizes[i];
        if (s == 8000LL) {
            if (ic < 3) idxp[ic++] = (const int*)d_in[i];
            continue;
        }
        for (int l = 0; l < 4; l++) {
            if (s == lsz[l]) {
                if (tc[l] == 0) tf[l] = (const float*)d_in[i];
                else            gf[l] = (const float*)d_in[i];
                tc[l]++;
                break;
            }
        }
    }

    k_init<<<(4 * BB * MAXN + 255) / 256, 256>>>();

    k_gather_all<<<dim3(1000, 24), 128>>>(tf[0], gf[0], idxp[0],
                                          tf[1], gf[1], idxp[1],
                                          tf[2], gf[2], idxp[2]);
    k_transpose3<<<dim3(32, 16, BB), dim3(32, 8)>>>(tf[3], gf[3]);
    k_norms3<<<dim3(32, BB), dim3(32, 8)>>>(tf[3], gf[3]);

    k_musum_all<<<dim3(8, MUSL, 32), dim3(64, 8)>>>();
    k_mufin_all<<<32, 512>>>();

    k_main<<<2448, 256>>>();

    k_minmeans_all<<<32, 256>>>();
    k_final<<<1, 32>>>((float*)d_out);
}

// round 17
// speedup vs baseline: 1.6485x; 1.6485x over previous
#include <cuda_runtime.h>
#include <float.h>
#include <math.h>

#define BB 8
#define MAXN 1024
#define MAXC 512
#define EPSV 1e-10f
#define MUSL 8

// level offsets into packed point buffers (floats)
__device__ __forceinline__ size_t lvl_off(int l) {
    return (l == 0) ? 0ul : (l == 1) ? 512000ul : (l == 2) ? 1536000ul : 3584000ul;
}

// ------------------------- scratch (static device globals) -----------------
__device__ __align__(128) float g_X[7778304];
__device__ __align__(128) float g_Y[7778304];
__device__ float g_xn[4 * BB * MAXN];
__device__ float g_yn[4 * BB * MAXN];
__device__ float g_rowmin[4 * BB * MAXN];
__device__ float g_colmin[4 * BB * MAXN];
__device__ float g_muxp[MUSL][4 * BB * MAXC];
__device__ float g_muyp[MUSL][4 * BB * MAXC];
__device__ float g_mux[4 * BB * MAXC];
__device__ float g_muy[4 * BB * MAXC];
__device__ float g_mud[4 * BB];
__device__ float g_covsum[4 * BB];
__device__ float g_m1[4 * BB];
__device__ float g_m2[4 * BB];

// ------------------------------ helpers ------------------------------------
__device__ __forceinline__ void atomicMinF(float* addr, float val) {
    if (val >= 0.f) atomicMin((int*)addr, __float_as_int(val));
    else            atomicMax((unsigned int*)addr, __float_as_uint(val));
}

__device__ __forceinline__ float blockReduceSum(float v, float* sbuf) {
    int t = threadIdx.x + threadIdx.y * blockDim.x;
    int nt = blockDim.x * blockDim.y;
    __syncthreads();
    sbuf[t] = v;
    __syncthreads();
    for (int s = nt >> 1; s > 0; s >>= 1) {
        if (t < s) sbuf[t] += sbuf[t + s];
        __syncthreads();
    }
    return sbuf[0];
}

__device__ __forceinline__ unsigned cvt_tf32(float x) {
    unsigned r;
    asm("cvt.rna.tf32.f32 %0, %1;" : "=r"(r) : "f"(x));
    return r;
}

__device__ __forceinline__ void mma_tf32(float& d0, float& d1, float& d2, float& d3,
                                         unsigned a0, unsigned a1, unsigned a2, unsigned a3,
                                         unsigned b0, unsigned b1) {
    asm("mma.sync.aligned.m16n8k8.row.col.f32.tf32.tf32.f32 "
        "{%0,%1,%2,%3},{%4,%5,%6,%7},{%8,%9},{%0,%1,%2,%3};"
        : "+f"(d0), "+f"(d1), "+f"(d2), "+f"(d3)
        : "r"(a0), "r"(a1), "r"(a2), "r"(a3), "r"(b0), "r"(b1));
}

// ------------------------------ init ----------------------------------------
__global__ void k_init() {
    int i = blockIdx.x * blockDim.x + threadIdx.x;
    if (i < 4 * BB * MAXN) {
        g_rowmin[i] = FLT_MAX;
        g_colmin[i] = FLT_MAX;
    }
    if (i < 4 * BB) g_covsum[i] = 0.f;
}

// --------------------- gather + norms (levels 0-2, one launch) --------------
__global__ void k_gather_all(const float* __restrict__ tf0, const float* __restrict__ gf0, const int* __restrict__ ix0,
                             const float* __restrict__ tf1, const float* __restrict__ gf1, const int* __restrict__ ix1,
                             const float* __restrict__ tf2, const float* __restrict__ gf2, const int* __restrict__ ix2) {
    __shared__ float sbuf[128];
    int i = blockIdx.x;
    int z = blockIdx.y;          // lvl*8 + b
    int lvl = z >> 3, b = z & 7;
    const float* tf; const float* gf; const int* idx; int c, hw;
    if (lvl == 0)      { tf = tf0; gf = gf0; idx = ix0; c = 64;  hw = 65536; }
    else if (lvl == 1) { tf = tf1; gf = gf1; idx = ix1; c = 128; hw = 16384; }
    else               { tf = tf2; gf = gf2; idx = ix2; c = 256; hw = 4096; }
    const int N = 1000;
    int p = idx[b * N + i];
    const float* ts = tf + (size_t)b * c * hw + p;
    const float* gs = gf + (size_t)b * c * hw + p;
    size_t base = lvl_off(lvl) + ((size_t)b * N + i) * c;
    float sx = 0.f, sy = 0.f;
    for (int ch = threadIdx.x; ch < c; ch += 128) {
        float v = ts[(size_t)ch * hw];
        float w = gs[(size_t)ch * hw];
        g_X[base + ch] = v;
        g_Y[base + ch] = w;
        sx += v * v;
        sy += w * w;
    }
    float tx_ = blockReduceSum(sx, sbuf);
    float ty_ = blockReduceSum(sy, sbuf);
    if (threadIdx.x == 0) {
        g_xn[z * MAXN + i] = sqrtf(tx_);
        g_yn[z * MAXN + i] = sqrtf(ty_);
    }
}

// ------------------------------ level-3 transpose ---------------------------
__global__ void k_transpose3(const float* __restrict__ tf, const float* __restrict__ gf) {
    __shared__ float st[32][33];
    __shared__ float sg[32][33];
    int b  = blockIdx.z;
    int i0 = blockIdx.x << 5;
    int c0 = blockIdx.y << 5;
    int tx = threadIdx.x;
    int ty = threadIdx.y;
    const float* tb = tf + ((size_t)(b * 512 + c0)) * 1024 + i0;
    const float* gb = gf + ((size_t)(b * 512 + c0)) * 1024 + i0;
    for (int r = ty; r < 32; r += 8) {
        st[r][tx] = tb[(size_t)r * 1024 + tx];
        sg[r][tx] = gb[(size_t)r * 1024 + tx];
    }
    __syncthreads();
    size_t base = 3584000ul + (size_t)b * 524288ul;
    for (int r = ty; r < 32; r += 8) {
        g_X[base + (size_t)(i0 + r) * 512 + c0 + tx] = st[tx][r];
        g_Y[base + (size_t)(i0 + r) * 512 + c0 + tx] = sg[tx][r];
    }
}

// ------------------------ norms for level 3 (original layout) ---------------
__global__ void k_norms3(const float* __restrict__ tf, const float* __restrict__ gf) {
    __shared__ float sx[8][33], sy[8][33];
    int b  = blockIdx.y;
    int i0 = blockIdx.x << 5;
    int tx = threadIdx.x, ty = threadIdx.y;
    const float* tb = tf + (size_t)b * 512 * 1024 + i0 + tx;
    const float* gb = gf + (size_t)b * 512 * 1024 + i0 + tx;
    float ax = 0.f, ay = 0.f;
    for (int ch = ty; ch < 512; ch += 8) {
        float v = tb[(size_t)ch * 1024]; ax += v * v;
        float w = gb[(size_t)ch * 1024]; ay += w * w;
    }
    sx[ty][tx] = ax;
    sy[ty][tx] = ay;
    __syncthreads();
    if (ty == 0) {
        float a = 0.f, c2 = 0.f;
#pragma unroll
        for (int k = 0; k < 8; k++) { a += sx[k][tx]; c2 += sy[k][tx]; }
        int z = 3 * BB + b;
        g_xn[z * MAXN + i0 + tx] = sqrtf(a);
        g_yn[z * MAXN + i0 + tx] = sqrtf(c2);
    }
}

// ------------------------------ mu partial sums (all levels) ----------------
__global__ void k_musum_all() {
    __shared__ float shx[8][64], shy[8][64];
    int z   = blockIdx.z;
    int lvl = z >> 3, b = z & 7;
    int c = 64 << lvl;
    int N = (lvl == 3) ? 1024 : 1000;
    if ((blockIdx.x << 6) >= c) return;
    int sl = blockIdx.y;
    int ch = (blockIdx.x << 6) + threadIdx.x;
    int len = (N + MUSL - 1) / MUSL;
    int r0 = sl * len;
    int r1 = min(N, r0 + len);
    const float* x = g_X + lvl_off(lvl) + (size_t)b * N * c + ch;
    const float* y = g_Y + lvl_off(lvl) + (size_t)b * N * c + ch;
    float sx = 0.f, sy = 0.f;
    for (int i = r0 + threadIdx.y; i < r1; i += 8) {
        sx += x[(size_t)i * c];
        sy += y[(size_t)i * c];
    }
    shx[threadIdx.y][threadIdx.x] = sx;
    shy[threadIdx.y][threadIdx.x] = sy;
    __syncthreads();
    if (threadIdx.y == 0) {
        float ax = 0.f, ay = 0.f;
#pragma unroll
        for (int k = 0; k < 8; k++) { ax += shx[k][threadIdx.x]; ay += shy[k][threadIdx.x]; }
        g_muxp[sl][z * MAXC + ch] = ax;
        g_muyp[sl][z * MAXC + ch] = ay;
    }
}

// ------------------------------ mu finalize + mu_d (all levels) -------------
__global__ void k_mufin_all() {
    __shared__ float sbuf[512];
    int z   = blockIdx.x;
    int lvl = z >> 3;
    int c = 64 << lvl;
    int N = (lvl == 3) ? 1024 : 1000;
    int p = threadIdx.x;
    float v = 0.f;
    if (p < c) {
        float sx = 0.f, sy = 0.f;
#pragma unroll
        for (int s = 0; s < MUSL; s++) {
            sx += g_muxp[s][z * MAXC + p];
            sy += g_muyp[s][z * MAXC + p];
        }
        float mx = sx / (float)N, my = sy / (float)N;
        g_mux[z * MAXC + p] = mx;
        g_muy[z * MAXC + p] = my;
        v = fabsf(mx - my);
    }
    float tot = blockReduceSum(v, sbuf);
    if (p == 0) g_mud[z] = tot / (float)c;
}

// ======================= fused main: tf32 MMA style + cov ===================
// Block schedule (expensive first): cov-l3(288), style-l3(512), cov-l2(80),
// style-l2(512), cov-l1(24), style-l1(512), cov-l0(8), style-l0(512) = 2448.
__global__ void __launch_bounds__(256) k_main() {
    __shared__ float SH[4608];
    int bid = blockIdx.x;
    int t = threadIdx.x;
    int w = t >> 5, lane = t & 31;
    int qr = lane >> 2, qc = lane & 3;

    bool isStyle;
    int lvl, b, rem;
    if (bid < 288)        { isStyle = false; lvl = 3; b = bid & 7;            rem = bid >> 3; }
    else if (bid < 800)   { isStyle = true;  lvl = 3; int s = bid - 288;  b = s >> 6; rem = s & 63; }
    else if (bid < 880)   { isStyle = false; lvl = 2; int s = bid - 800;  b = s & 7;  rem = s >> 3; }
    else if (bid < 1392)  { isStyle = true;  lvl = 2; int s = bid - 880;  b = s >> 6; rem = s & 63; }
    else if (bid < 1416)  { isStyle = false; lvl = 1; int s = bid - 1392; b = s & 7;  rem = s >> 3; }
    else if (bid < 1928)  { isStyle = true;  lvl = 1; int s = bid - 1416; b = s >> 6; rem = s & 63; }
    else if (bid < 1936)  { isStyle = false; lvl = 0; int s = bid - 1928; b = s & 7;  rem = 0; }
    else                  { isStyle = true;  lvl = 0; int s = bid - 1936; b = s >> 6; rem = s & 63; }

    int c = 64 << lvl;
    int N = (lvl == 3) ? 1024 : 1000;
    int zi = lvl * BB + b;
    const float* X = g_X + lvl_off(lvl) + (size_t)b * N * c;
    const float* Y = g_Y + lvl_off(lvl) + (size_t)b * N * c;
    float4 z4 = make_float4(0.f, 0.f, 0.f, 0.f);

    if (isStyle) {
        // ---- style: 128x128 tile, BK=8, double-buffered tf32 MMA -----------
        // warp grid: wm = w&1 (2 x 64 rows), wn = w>>1 (4 x 32 cols)
        unsigned* As = (unsigned*)SH;           // [2][8][132]
        unsigned* Bs = (unsigned*)SH + 2112;    // [2][8][132]
        float* sRow  = SH + 4224;               // 128
        float* sCol  = SH + 4352;               // 128
        int wm = w & 1, wn = w >> 1;
        int i0 = (rem >> 3) << 7;
        int j0 = (rem & 7) << 7;
        int lr = t >> 1;
        int lk = (t & 1) << 2;
        int gi = i0 + lr, gj = j0 + lr;
        const float* xp = X + (size_t)gi * c + lk;
        const float* yp = Y + (size_t)gj * c + lk;

        float acc[4][4][4];
#pragma unroll
        for (int mf = 0; mf < 4; mf++)
#pragma unroll
            for (int nf = 0; nf < 4; nf++)
#pragma unroll
                for (int e = 0; e < 4; e++) acc[mf][nf][e] = 0.f;

        if (t < 128) { sRow[t] = FLT_MAX; sCol[t] = FLT_MAX; }

        // preload tile 0 into buffer 0
        {
            float4 cA = (gi < N) ? *reinterpret_cast<const float4*>(xp) : z4;
            float4 cB = (gj < N) ? *reinterpret_cast<const float4*>(yp) : z4;
            As[(lk + 0) * 132 + lr] = cvt_tf32(cA.x); As[(lk + 1) * 132 + lr] = cvt_tf32(cA.y);
            As[(lk + 2) * 132 + lr] = cvt_tf32(cA.z); As[(lk + 3) * 132 + lr] = cvt_tf32(cA.w);
            Bs[(lk + 0) * 132 + lr] = cvt_tf32(cB.x); Bs[(lk + 1) * 132 + lr] = cvt_tf32(cB.y);
            Bs[(lk + 2) * 132 + lr] = cvt_tf32(cB.z); Bs[(lk + 3) * 132 + lr] = cvt_tf32(cB.w);
        }
        __syncthreads();

        for (int k0 = 0; k0 < c; k0 += 8) {
            int buf = (k0 >> 3) & 1;
            int o = buf * 1056;
            int kn = k0 + 8;
            float4 nA = z4, nB = z4;
            if (kn < c) {
                nA = (gi < N) ? *reinterpret_cast<const float4*>(xp + kn) : z4;
                nB = (gj < N) ? *reinterpret_cast<const float4*>(yp + kn) : z4;
            }
            // fragment loads
            unsigned af[4][4], bf[4][2];
#pragma unroll
            for (int mf = 0; mf < 4; mf++) {
                int m = wm * 64 + mf * 16 + qr;
                af[mf][0] = As[o + qc * 132 + m];
                af[mf][1] = As[o + qc * 132 + m + 8];
                af[mf][2] = As[o + (qc + 4) * 132 + m];
                af[mf][3] = As[o + (qc + 4) * 132 + m + 8];
            }
#pragma unroll
            for (int nf = 0; nf < 4; nf++) {
                int n = wn * 32 + nf * 8 + qr;
                bf[nf][0] = Bs[o + qc * 132 + n];
                bf[nf][1] = Bs[o + (qc + 4) * 132 + n];
            }
#pragma unroll
            for (int mf = 0; mf < 4; mf++)
#pragma unroll
                for (int nf = 0; nf < 4; nf++)
                    mma_tf32(acc[mf][nf][0], acc[mf][nf][1], acc[mf][nf][2], acc[mf][nf][3],
                             af[mf][0], af[mf][1], af[mf][2], af[mf][3],
                             bf[nf][0], bf[nf][1]);
            if (kn < c) {
                unsigned* An = As + (o ^ 1056);
                unsigned* Bn = Bs + (o ^ 1056);
                An[(lk + 0) * 132 + lr] = cvt_tf32(nA.x); An[(lk + 1) * 132 + lr] = cvt_tf32(nA.y);
                An[(lk + 2) * 132 + lr] = cvt_tf32(nA.z); An[(lk + 3) * 132 + lr] = cvt_tf32(nA.w);
                Bn[(lk + 0) * 132 + lr] = cvt_tf32(nB.x); Bn[(lk + 1) * 132 + lr] = cvt_tf32(nB.y);
                Bn[(lk + 2) * 132 + lr] = cvt_tf32(nB.z); Bn[(lk + 3) * 132 + lr] = cvt_tf32(nB.w);
            }
            __syncthreads();
        }

        // epilogue: cos-dist + row/col mins
        float rn[8], cn[8];
#pragma unroll
        for (int ri = 0; ri < 8; ri++) {
            int i = i0 + wm * 64 + (ri >> 1) * 16 + (ri & 1) * 8 + qr;
            rn[ri] = (i < N) ? g_xn[zi * MAXN + i] : 0.f;
        }
#pragma unroll
        for (int ci = 0; ci < 8; ci++) {
            int j = j0 + wn * 32 + (ci >> 1) * 8 + qc * 2 + (ci & 1);
            cn[ci] = (j < N) ? g_yn[zi * MAXN + j] : 0.f;
        }
        float rmin[8], cmin[8];
#pragma unroll
        for (int q = 0; q < 8; q++) { rmin[q] = FLT_MAX; cmin[q] = FLT_MAX; }
#pragma unroll
        for (int mf = 0; mf < 4; mf++)
#pragma unroll
            for (int nf = 0; nf < 4; nf++)
#pragma unroll
                for (int e = 0; e < 4; e++) {
                    int ri = mf * 2 + (e >> 1);
                    int ci = nf * 2 + (e & 1);
                    int i = i0 + wm * 64 + mf * 16 + qr + (e >> 1) * 8;
                    int j = j0 + wn * 32 + nf * 8 + qc * 2 + (e & 1);
                    float d = FLT_MAX;
                    if (i < N && j < N)
                        d = 1.f - acc[mf][nf][e] / ((rn[ri] + EPSV) * (cn[ci] + EPSV));
                    rmin[ri] = fminf(rmin[ri], d);
                    cmin[ci] = fminf(cmin[ci], d);
                }
#pragma unroll
        for (int ri = 0; ri < 8; ri++)
            atomicMinF(&sRow[wm * 64 + (ri >> 1) * 16 + (ri & 1) * 8 + qr], rmin[ri]);
#pragma unroll
        for (int ci = 0; ci < 8; ci++)
            atomicMinF(&sCol[wn * 32 + (ci >> 1) * 8 + qc * 2 + (ci & 1)], cmin[ci]);
        __syncthreads();

        if (t < 128) {
            if (i0 + t < N) atomicMinF(&g_rowmin[zi * MAXN + i0 + t], sRow[t]);
            if (j0 + t < N) atomicMinF(&g_colmin[zi * MAXN + j0 + t], sCol[t]);
        }
    } else {
        // ---- cov: 64x64 tile of (p,q), tp<=tq, BK=16, tf32 MMA -------------
        // warp grid: wm = w&1 (2 x 32 rows), wn = w>>1 (4 x 16 cols)
        unsigned* Xp = (unsigned*)SH;            // [16][68]
        unsigned* Xq = (unsigned*)SH + 1088;
        unsigned* Yp = (unsigned*)SH + 2176;
        unsigned* Yq = (unsigned*)SH + 3264;
        float* sbuf  = SH + 4352;                // 256
        int wm = w & 1, wn = w >> 1;

        int T = c >> 6;
        int tp = 0, r2 = rem;
        while (r2 >= T - tp) { r2 -= (T - tp); tp++; }
        int tq = tp + r2;
        int p0 = tp << 6, q0 = tq << 6;

        int lrow = t >> 4;
        int lcol = (t & 15) << 2;

        float accx[2][2][4], accy[2][2][4];
#pragma unroll
        for (int mf = 0; mf < 2; mf++)
#pragma unroll
            for (int nf = 0; nf < 2; nf++)
#pragma unroll
                for (int e = 0; e < 4; e++) { accx[mf][nf][e] = 0.f; accy[mf][nf][e] = 0.f; }

        for (int k0 = 0; k0 < N; k0 += 16) {
            int i = k0 + lrow;
            float4 v0 = z4, v1 = z4, v2 = z4, v3 = z4;
            if (i < N) {
                const float* xr = X + (size_t)i * c;
                const float* yr = Y + (size_t)i * c;
                v0 = *reinterpret_cast<const float4*>(xr + p0 + lcol);
                v1 = *reinterpret_cast<const float4*>(xr + q0 + lcol);
                v2 = *reinterpret_cast<const float4*>(yr + p0 + lcol);
                v3 = *reinterpret_cast<const float4*>(yr + q0 + lcol);
            }
            int sb = lrow * 68 + lcol;
            Xp[sb + 0] = cvt_tf32(v0.x); Xp[sb + 1] = cvt_tf32(v0.y); Xp[sb + 2] = cvt_tf32(v0.z); Xp[sb + 3] = cvt_tf32(v0.w);
            Xq[sb + 0] = cvt_tf32(v1.x); Xq[sb + 1] = cvt_tf32(v1.y); Xq[sb + 2] = cvt_tf32(v1.z); Xq[sb + 3] = cvt_tf32(v1.w);
            Yp[sb + 0] = cvt_tf32(v2.x); Yp[sb + 1] = cvt_tf32(v2.y); Yp[sb + 2] = cvt_tf32(v2.z); Yp[sb + 3] = cvt_tf32(v2.w);
            Yq[sb + 0] = cvt_tf32(v3.x); Yq[sb + 1] = cvt_tf32(v3.y); Yq[sb + 2] = cvt_tf32(v3.z); Yq[sb + 3] = cvt_tf32(v3.w);
            __syncthreads();
#pragma unroll
            for (int kof = 0; kof < 16; kof += 8) {
                unsigned axf[2][4], bxf[2][2], ayf[2][4], byf[2][2];
#pragma unroll
                for (int mf = 0; mf < 2; mf++) {
                    int m = wm * 32 + mf * 16 + qr;
                    axf[mf][0] = Xp[(kof + qc) * 68 + m];
                    axf[mf][1] = Xp[(kof + qc) * 68 + m + 8];
                    axf[mf][2] = Xp[(kof + qc + 4) * 68 + m];
                    axf[mf][3] = Xp[(kof + qc + 4) * 68 + m + 8];
                    ayf[mf][0] = Yp[(kof + qc) * 68 + m];
                    ayf[mf][1] = Yp[(kof + qc) * 68 + m + 8];
                    ayf[mf][2] = Yp[(kof + qc + 4) * 68 + m];
                    ayf[mf][3] = Yp[(kof + qc + 4) * 68 + m + 8];
                }
#pragma unroll
                for (int nf = 0; nf < 2; nf++) {
                    int n = wn * 16 + nf * 8 + qr;
                    bxf[nf][0] = Xq[(kof + qc) * 68 + n];
                    bxf[nf][1] = Xq[(kof + qc + 4) * 68 + n];
                    byf[nf][0] = Yq[(kof + qc) * 68 + n];
                    byf[nf][1] = Yq[(kof + qc + 4) * 68 + n];
                }
#pragma unroll
                for (int mf = 0; mf < 2; mf++)
#pragma unroll
                    for (int nf = 0; nf < 2; nf++) {
                        mma_tf32(accx[mf][nf][0], accx[mf][nf][1], accx[mf][nf][2], accx[mf][nf][3],
                                 axf[mf][0], axf[mf][1], axf[mf][2], axf[mf][3],
                                 bxf[nf][0], bxf[nf][1]);
                        mma_tf32(accy[mf][nf][0], accy[mf][nf][1], accy[mf][nf][2], accy[mf][nf][3],
                                 ayf[mf][0], ayf[mf][1], ayf[mf][2], ayf[mf][3],
                                 byf[nf][0], byf[nf][1]);
                    }
            }
            __syncthreads();
        }

        float fn = (float)N;
        float inv = 1.f / (fn - 1.f);
        float mxp[4], myp[4], mxq[4], myq[4];
#pragma unroll
        for (int ri = 0; ri < 4; ri++) {
            int p = p0 + wm * 32 + (ri >> 1) * 16 + (ri & 1) * 8 + qr;
            mxp[ri] = g_mux[zi * MAXC + p];
            myp[ri] = g_muy[zi * MAXC + p];
        }
#pragma unroll
        for (int ci = 0; ci < 4; ci++) {
            int q = q0 + wn * 16 + (ci >> 1) * 8 + qc * 2 + (ci & 1);
            mxq[ci] = g_mux[zi * MAXC + q];
            myq[ci] = g_muy[zi * MAXC + q];
        }
        float s = 0.f;
#pragma unroll
        for (int mf = 0; mf < 2; mf++)
#pragma unroll
            for (int nf = 0; nf < 2; nf++)
#pragma unroll
                for (int e = 0; e < 4; e++) {
                    int ri = mf * 2 + (e >> 1);
                    int ci = nf * 2 + (e & 1);
                    float gx = accx[mf][nf][e] - fn * mxp[ri] * mxq[ci];
                    float gy = accy[mf][nf][e] - fn * myp[ri] * myq[ci];
                    s += fabsf((gx - gy) * inv);
                }
        if (tp != tq) s *= 2.f;
        float tot = blockReduceSum(s, sbuf);
        if (t == 0) atomicAdd(&g_covsum[zi], tot);
    }
}

// ------------------------------ style means (all levels) --------------------
__global__ void k_minmeans_all() {
    __shared__ float sbuf[256];
    int z = blockIdx.x;
    int lvl = z >> 3;
    int N = (lvl == 3) ? 1024 : 1000;
    const float* rm = g_rowmin + (size_t)z * MAXN;
    const float* cm = g_colmin + (size_t)z * MAXN;
    float s1 = 0.f, s2 = 0.f;
    for (int i = threadIdx.x; i < N; i += 256) { s1 += rm[i]; s2 += cm[i]; }
    float t1 = blockReduceSum(s1, sbuf);
    float t2 = blockReduceSum(s2, sbuf);
    if (threadIdx.x == 0) {
        g_m1[z] = t1 / (float)N;
        g_m2[z] = t2 / (float)N;
    }
}

// ------------------------------ final ---------------------------------------
__global__ void k_final(float* out) {
    int t = threadIdx.x;
    float v = 0.f;
    if (t < 32) {
        int lvl = t >> 3;
        float cc = (float)(64 << lvl);
        float style = fmaxf(g_m1[t], g_m2[t]);
        v = style + g_mud[t] + g_covsum[t] / (cc * cc);
    }
#pragma unroll
    for (int o = 16; o > 0; o >>= 1) v += __shfl_down_sync(0xffffffff, v, o);
    if (t == 0) out[0] = v / (float)BB;
}

// ------------------------------ launch --------------------------------------
extern "C" void kernel_launch(void* const* d_in, const int* in_sizes, int n_in,
                              void* d_out, int out_size) {
    (void)out_size;
    const float* tf[4] = {0, 0, 0, 0};
    const float* gf[4] = {0, 0, 0, 0};
    const int* idxp[3] = {0, 0, 0};
    int tc[4] = {0, 0, 0, 0}, ic = 0;
    const long long lsz[4] = {33554432LL, 16777216LL, 8388608LL, 4194304LL};
    for (int i = 0; i < n_in; i++) {
        long long s = in_sizes[i];
        if (s == 8000LL) {
            if (ic < 3) idxp[ic++] = (const int*)d_in[i];
            continue;
        }
        for (int l = 0; l < 4; l++) {
            if (s == lsz[l]) {
                if (tc[l] == 0) tf[l] = (const float*)d_in[i];
                else            gf[l] = (const float*)d_in[i];
                tc[l]++;
                break;
            }
        }
    }

    k_init<<<(4 * BB * MAXN + 255) / 256, 256>>>();

    k_gather_all<<<dim3(1000, 24), 128>>>(tf[0], gf[0], idxp[0],
                                          tf[1], gf[1], idxp[1],
                                          tf[2], gf[2], idxp[2]);
    k_transpose3<<<dim3(32, 16, BB), dim3(32, 8)>>>(tf[3], gf[3]);
    k_norms3<<<dim3(32, BB), dim3(32, 8)>>>(tf[3], gf[3]);

    k_musum_all<<<dim3(8, MUSL, 32), dim3(64, 8)>>>();
    k_mufin_all<<<32, 512>>>();

    k_main<<<2448, 256>>>();

    k_minmeans_all<<<32, 256>>>();
    k_final<<<1, 32>>>((float*)d_out);
}